// round 5
// baseline (speedup 1.0000x reference)
#include <cuda_runtime.h>

#define DK   8
#define SS   1024
#define BB   8
#define NH   8
#define BH   (BB * NH)          // 64
#define NROWS (BB * SS * NH)    // 65536 q-rows total
#define ABLK 296                // attn blocks: exactly 2 per SM, one wave
#define RPB  222                // rows per attn block (296*222 >= 65536)

// Scratch: attention out in ROW-FEATURE layout [b*1024+s][h*8+d]  (2 MB)
__device__ float g_ao[BB * SS * 64];

// ---------------------------------------------------------------------------
// f32x2 packed-math helpers (sm_10x; untyped .b64 regs -> "l" constraints)
// ---------------------------------------------------------------------------
typedef unsigned long long u64;

__device__ __forceinline__ u64 ffma2(u64 a, u64 b, u64 c) {
    u64 r; asm("fma.rn.f32x2 %0,%1,%2,%3;" : "=l"(r) : "l"(a), "l"(b), "l"(c)); return r;
}
__device__ __forceinline__ u64 fmul2(u64 a, u64 b) {
    u64 r; asm("mul.rn.f32x2 %0,%1,%2;" : "=l"(r) : "l"(a), "l"(b)); return r;
}
__device__ __forceinline__ u64 fadd2(u64 a, u64 b) {
    u64 r; asm("add.rn.f32x2 %0,%1,%2;" : "=l"(r) : "l"(a), "l"(b)); return r;
}
__device__ __forceinline__ u64 pk2(float lo, float hi) {
    u64 r; asm("mov.b64 %0,{%1,%2};" : "=l"(r) : "f"(lo), "f"(hi)); return r;
}
__device__ __forceinline__ void upk2(u64 v, float& lo, float& hi) {
    asm("mov.b64 {%0,%1},%2;" : "=f"(lo), "=f"(hi) : "l"(v));
}
__device__ __forceinline__ float ex2(float x) {
    float r; asm("ex2.approx.f32 %0,%1;" : "=f"(r) : "f"(x)); return r;
}

// ---------------------------------------------------------------------------
// Fused qlayer + attention, BALANCED partition.
// Block k owns global q-rows [k*222, k*222+222); those span <=2 head tiles.
// For each spanned head: rebuild the transposed K tile (qlayer = prefix
// products of cos(x+phi)) in smem, then threads whose row lies in that head
// run the softmax(QK)V mainloop.  |score|<=2.83 -> plain sum-of-exp.
// q pre-scaled by log2(e)/sqrt(8) so exp is a raw ex2.approx.
// ---------------------------------------------------------------------------
__global__ __launch_bounds__(256) void attn_kernel(const float* __restrict__ x,
                                                   const float* __restrict__ phi) {
    __shared__ float smt[8 * SS];        // 32 KB, smt[d*1024 + j]

    const int tid = threadIdx.x;
    const int row_lo = blockIdx.x * RPB;
    const int row_hi = min(row_lo + RPB, NROWS);
    const int myrow  = row_lo + tid;     // this thread's global row (may be out)

    float ph0 = phi[0], ph1 = phi[1], ph2 = phi[2], ph3 = phi[3];
    float ph4 = phi[4], ph5 = phi[5], ph6 = phi[6], ph7 = phi[7];
    const float SC = 0.35355339059327373f * 1.4426950408889634f;

    const int bh_first = row_lo >> 10;
    const int bh_last  = (row_hi - 1) >> 10;

    for (int bh = bh_first; bh <= bh_last; bh++) {
        const int b = bh >> 3, h = bh & 7;

        if (bh != bh_first) __syncthreads();   // protect previous tile readers

        // ---- build transposed qlayer tile for this head ----
        #pragma unroll
        for (int it = 0; it < 4; it++) {
            int s = tid + it * 256;
            const float4* xp = (const float4*)(x + ((size_t)((b << 10) + s) << 6) + (h << 3));
            float4 xa = xp[0];
            float4 xb = xp[1];
            float c0 = __cosf(xa.x + ph0);
            float c1 = __cosf(xa.y + ph1);
            float c2 = __cosf(xa.z + ph2);
            float c3 = __cosf(xa.w + ph3);
            float c4 = __cosf(xb.x + ph4);
            float c5 = __cosf(xb.y + ph5);
            float c6 = __cosf(xb.z + ph6);
            float c7 = __cosf(xb.w + ph7);
            float p1 = c0 * c1;
            float p2 = p1 * c2;
            float p3 = p2 * c3;
            float p4 = p3 * c4;
            float p5 = p4 * c5;
            float p6 = p5 * c6;
            float p7 = p6 * c7;
            float t = c1 * c2;
            t *= c3; t *= c4; t *= c5; t *= c6; t *= c7;
            smt[0 * SS + s] = t;
            smt[1 * SS + s] = p1;
            smt[2 * SS + s] = p2;
            smt[3 * SS + s] = p3;
            smt[4 * SS + s] = p4;
            smt[5 * SS + s] = p5;
            smt[6 * SS + s] = p6;
            smt[7 * SS + s] = p7;
        }
        __syncthreads();

        if (myrow < row_hi && (myrow >> 10) == bh) {
            const int s = myrow & 1023;

            u64 Q[8];
            #pragma unroll
            for (int d = 0; d < 8; d++) {
                float q = smt[d * SS + s] * SC;
                Q[d] = pk2(q, q);
            }

            u64 A[8];
            #pragma unroll
            for (int d = 0; d < 8; d++) A[d] = 0ull;
            u64 L = 0ull;

            #pragma unroll 2
            for (int j = 0; j < SS; j += 4) {
                u64 Ka[8], Kb[8];
                #pragma unroll
                for (int d = 0; d < 8; d++) {
                    ulonglong2 kk = *(const ulonglong2*)&smt[d * SS + j];
                    Ka[d] = kk.x;
                    Kb[d] = kk.y;
                }

                u64 Sa = fmul2(Q[0], Ka[0]);
                u64 Sb = fmul2(Q[0], Kb[0]);
                #pragma unroll
                for (int d = 1; d < 8; d++) {
                    Sa = ffma2(Q[d], Ka[d], Sa);
                    Sb = ffma2(Q[d], Kb[d], Sb);
                }

                float s0, s1, s2, s3;
                upk2(Sa, s0, s1);
                upk2(Sb, s2, s3);
                u64 Pa = pk2(ex2(s0), ex2(s1));
                u64 Pb = pk2(ex2(s2), ex2(s3));

                L = fadd2(L, Pa);
                L = fadd2(L, Pb);

                #pragma unroll
                for (int d = 0; d < 8; d++) {
                    A[d] = ffma2(Pa, Ka[d], A[d]);
                    A[d] = ffma2(Pb, Kb[d], A[d]);
                }
            }

            float la, lb;
            upk2(L, la, lb);
            float inv = 1.f / (la + lb);

            float o[8];
            #pragma unroll
            for (int d = 0; d < 8; d++) {
                float xlo, xhi;
                upk2(A[d], xlo, xhi);
                o[d] = (xlo + xhi) * inv;
            }

            float4* ao4 = (float4*)&g_ao[((((size_t)b << 10) + s) << 6) + (h << 3)];
            ao4[0] = make_float4(o[0], o[1], o[2], o[3]);
            ao4[1] = make_float4(o[4], o[5], o[6], o[7]);
        }
    }
}

// ---------------------------------------------------------------------------
// Epilogue: out = ao @ W^T + b.  W rows in REGISTERS (lane owns column e);
// activations staged linearly in smem, read via warp-broadcast ld.shared.v4.
// 256 blocks x 32 rows; 8 warps = 4 row-groups x 2 col-halves; 8 rows/warp.
// ---------------------------------------------------------------------------
__global__ __launch_bounds__(256) void epilogue_kernel(const float* __restrict__ W,
                                                       const float* __restrict__ bias,
                                                       float* __restrict__ out) {
    __shared__ float ssin[32 * 64];      // 8 KB

    const int tid = threadIdx.x;
    const int row0 = blockIdx.x * 32;

    // stage 32 rows of activations (perfectly linear)
    const float4* src = (const float4*)(g_ao + (size_t)row0 * 64);
    float4* dst = (float4*)ssin;
    #pragma unroll
    for (int i = 0; i < 2; i++)
        dst[tid + i * 256] = src[tid + i * 256];

    // this lane's output column + its W row in registers
    const int w = tid >> 5, lane = tid & 31;
    const int e = (w & 1) * 32 + lane;
    float wreg[64];
    const float4* wsrc = (const float4*)(W + e * 64);
    #pragma unroll
    for (int i = 0; i < 16; i++) {
        float4 v = wsrc[i];
        wreg[4 * i + 0] = v.x;
        wreg[4 * i + 1] = v.y;
        wreg[4 * i + 2] = v.z;
        wreg[4 * i + 3] = v.w;
    }
    const float be = bias[e];
    __syncthreads();

    const int rbase = (w >> 1) * 8;      // 8 rows per warp
    #pragma unroll
    for (int rr = 0; rr < 8; rr++) {
        int r = rbase + rr;
        const float4* srow = (const float4*)&ssin[r * 64];
        float acc = be;
        #pragma unroll
        for (int i = 0; i < 16; i++) {
            float4 sv = srow[i];         // broadcast: all lanes same address
            acc += sv.x * wreg[4 * i + 0];
            acc += sv.y * wreg[4 * i + 1];
            acc += sv.z * wreg[4 * i + 2];
            acc += sv.w * wreg[4 * i + 3];
        }
        out[(row0 + r) * 64 + e] = acc;  // lanes e consecutive -> coalesced
    }
}

// ---------------------------------------------------------------------------
extern "C" void kernel_launch(void* const* d_in, const int* in_sizes, int n_in,
                              void* d_out, int out_size) {
    const float* x    = (const float*)d_in[0];
    const float* phi  = (const float*)d_in[1];
    const float* W    = (const float*)d_in[2];
    const float* bias = (const float*)d_in[3];
    float* out = (float*)d_out;

    attn_kernel<<<ABLK, 256>>>(x, phi);
    epilogue_kernel<<<(BB * SS) / 32, 256>>>(W, bias, out);
}

// round 6
// speedup vs baseline: 2.5916x; 2.5916x over previous
#include <cuda_runtime.h>
#include <cuda_fp16.h>

#define SS   1024
#define BB   8
#define NH   8
#define BH   (BB * NH)          // 64

// Scratch: attention out in ROW-FEATURE layout [b*1024+s][h*8+d]  (2 MB)
__device__ float g_ao[BB * SS * 64];

// smem partition (dynamic): kh[1024][8] half, kl[1024][8] half, vt[8][1032] half
#define SM_KH 0
#define SM_KL 16384
#define SM_VT 32768
#define VT_STRIDE 1032              // halves per d-row: bank-free PV b-frags
#define SMEM_BYTES (32768 + 8 * VT_STRIDE * 2)   // 49280

__device__ __forceinline__ float ex2(float x) {
    float r; asm("ex2.approx.f32 %0,%1;" : "=f"(r) : "f"(x)); return r;
}
__device__ __forceinline__ unsigned h2pk(float hi, float lo) {
    unsigned r; asm("cvt.rn.f16x2.f32 %0,%1,%2;" : "=r"(r) : "f"(hi), "f"(lo)); return r;
}
__device__ __forceinline__ void mma_16x8x8(float& c0, float& c1, float& c2, float& c3,
                                           unsigned a0, unsigned a1, unsigned b0) {
    asm("mma.sync.aligned.m16n8k8.row.col.f32.f16.f16.f32 "
        "{%0,%1,%2,%3},{%4,%5},{%6},{%0,%1,%2,%3};"
        : "+f"(c0), "+f"(c1), "+f"(c2), "+f"(c3)
        : "r"(a0), "r"(a1), "r"(b0));
}
__device__ __forceinline__ void mma_16x8x16(float& c0, float& c1, float& c2, float& c3,
                                            unsigned a0, unsigned a1, unsigned a2, unsigned a3,
                                            unsigned b0, unsigned b1) {
    asm("mma.sync.aligned.m16n8k16.row.col.f32.f16.f16.f32 "
        "{%0,%1,%2,%3},{%4,%5,%6,%7},{%8,%9},{%0,%1,%2,%3};"
        : "+f"(c0), "+f"(c1), "+f"(c2), "+f"(c3)
        : "r"(a0), "r"(a1), "r"(a2), "r"(a3), "r"(b0), "r"(b1));
}

// ---------------------------------------------------------------------------
// Fused qlayer + flash-attention via mma.sync (fp16-split, f32 accum).
// Grid: 512 blocks = 64 heads x 8 row-tiles; 256 thr = 8 warps x 16 q-rows.
// qlayer == prefix products of cos(x+phi); K == V == proj; q = k*log2e/sqrt8.
// QK = qh*kh + qh*kl + ql*kh (3 mma, err ~1e-6). exp via ex2. P fp16 feeds
// PV mma directly (C-frag cols == A-frag cols for m16n8k16).
// ---------------------------------------------------------------------------
__global__ __launch_bounds__(256) void attn_kernel(const float* __restrict__ x,
                                                   const float* __restrict__ phi) {
    extern __shared__ char dynsmem[];
    __half*  kh = (__half*)(dynsmem + SM_KH);       // [j][8] row-major
    __half*  kl = (__half*)(dynsmem + SM_KL);       // [j][8] row-major
    __half*  vt = (__half*)(dynsmem + SM_VT);       // [d][VT_STRIDE]
    const unsigned* khw = (const unsigned*)kh;      // half2 words: [j*4 + p]
    const unsigned* klw = (const unsigned*)kl;
    const unsigned* vtw = (const unsigned*)vt;      // [d*516 + j/2]

    const int bh = blockIdx.x >> 3;
    const int b = bh >> 3, h = bh & 7;
    const int tid = threadIdx.x;

    float ph0 = phi[0], ph1 = phi[1], ph2 = phi[2], ph3 = phi[3];
    float ph4 = phi[4], ph5 = phi[5], ph6 = phi[6], ph7 = phi[7];

    // ---- prologue: qlayer -> kh/kl (row-major) and vt (transposed) ----
    #pragma unroll
    for (int it = 0; it < 4; it++) {
        int s = tid + it * 256;
        const float4* xp = (const float4*)(x + ((size_t)((b << 10) + s) << 6) + (h << 3));
        float4 xa = xp[0];
        float4 xb = xp[1];
        float k0 = __cosf(xa.x + ph0);
        float c1 = __cosf(xa.y + ph1);
        float c2 = __cosf(xa.z + ph2);
        float c3 = __cosf(xa.w + ph3);
        float c4 = __cosf(xb.x + ph4);
        float c5 = __cosf(xb.y + ph5);
        float c6 = __cosf(xb.z + ph6);
        float c7 = __cosf(xb.w + ph7);
        float kv[8];
        kv[1] = k0 * c1;
        kv[2] = kv[1] * c2;
        kv[3] = kv[2] * c3;
        kv[4] = kv[3] * c4;
        kv[5] = kv[4] * c5;
        kv[6] = kv[5] * c6;
        kv[7] = kv[6] * c7;
        float t = c1 * c2;
        t *= c3; t *= c4; t *= c5; t *= c6; t *= c7;
        kv[0] = t;
        #pragma unroll
        for (int d = 0; d < 8; d++) {
            __half hi = __float2half_rn(kv[d]);
            __half lo = __float2half_rn(kv[d] - __half2float(hi));
            kh[s * 8 + d] = hi;
            kl[s * 8 + d] = lo;
            vt[d * VT_STRIDE + s] = hi;   // V in fp16 (hi part; err averages out)
        }
    }
    __syncthreads();

    // ---- per-warp Q fragments (rows r0+lane/4, r0+lane/4+8) ----
    const int wid = tid >> 5, lane = tid & 31;
    const int r0 = ((blockIdx.x & 7) << 7) + (wid << 4);
    const int qr = lane >> 2, qm = lane & 3;
    const float SC = 0.35355339059327373f * 1.4426950408889634f;

    unsigned qh_a0, qh_a1, ql_a0, ql_a1;
    {
        #pragma unroll
        for (int half_ = 0; half_ < 2; half_++) {
            int row = r0 + qr + half_ * 8;
            unsigned wh = khw[row * 4 + qm];
            unsigned wl = klw[row * 4 + qm];
            __half2 hh = *(__half2*)&wh, hl = *(__half2*)&wl;
            float q0 = (__half2float(hh.x) + __half2float(hl.x)) * SC;
            float q1 = (__half2float(hh.y) + __half2float(hl.y)) * SC;
            __half q0h = __float2half_rn(q0);
            __half q1h = __float2half_rn(q1);
            float q0r = q0 - __half2float(q0h);
            float q1r = q1 - __half2float(q1h);
            unsigned ah = h2pk(__half2float(q1h), __half2float(q0h));
            unsigned al = h2pk(q1r, q0r);
            if (half_ == 0) { qh_a0 = ah; ql_a0 = al; }
            else            { qh_a1 = ah; ql_a1 = al; }
        }
    }

    float o0 = 0.f, o1 = 0.f, o2 = 0.f, o3 = 0.f;   // O accum (16x8)
    float L0 = 0.f, L1 = 0.f;                        // row-sum partials

    const int vbase = (lane >> 2) * (VT_STRIDE / 2) + (lane & 3);

    #pragma unroll 2
    for (int c = 0; c < SS; c += 16) {
        // ---- QK chunk A (keys c..c+7) ----
        unsigned bhA = khw[c * 4 + lane];
        unsigned blA = klw[c * 4 + lane];
        float sA0 = 0.f, sA1 = 0.f, sA2 = 0.f, sA3 = 0.f;
        mma_16x8x8(sA0, sA1, sA2, sA3, qh_a0, qh_a1, bhA);
        mma_16x8x8(sA0, sA1, sA2, sA3, qh_a0, qh_a1, blA);
        mma_16x8x8(sA0, sA1, sA2, sA3, ql_a0, ql_a1, bhA);

        // ---- QK chunk B (keys c+8..c+15) ----
        unsigned bhB = khw[(c + 8) * 4 + lane];
        unsigned blB = klw[(c + 8) * 4 + lane];
        float sB0 = 0.f, sB1 = 0.f, sB2 = 0.f, sB3 = 0.f;
        mma_16x8x8(sB0, sB1, sB2, sB3, qh_a0, qh_a1, bhB);
        mma_16x8x8(sB0, sB1, sB2, sB3, qh_a0, qh_a1, blB);
        mma_16x8x8(sB0, sB1, sB2, sB3, ql_a0, ql_a1, bhB);

        // ---- softmax weights (no max-sub: |s| <= 4.1 in log2 units) ----
        float pA0 = ex2(sA0), pA1 = ex2(sA1), pA2 = ex2(sA2), pA3 = ex2(sA3);
        float pB0 = ex2(sB0), pB1 = ex2(sB1), pB2 = ex2(sB2), pB3 = ex2(sB3);
        L0 += (pA0 + pA1) + (pB0 + pB1);
        L1 += (pA2 + pA3) + (pB2 + pB3);

        // ---- P fp16 A-frag (C-frag cols 2m,2m+1 == A-frag cols) ----
        unsigned a0 = h2pk(pA1, pA0);
        unsigned a1 = h2pk(pA3, pA2);
        unsigned a2 = h2pk(pB1, pB0);
        unsigned a3 = h2pk(pB3, pB2);

        // ---- PV: O += P(16x16) * V(16x8) ----
        unsigned vb0 = vtw[vbase + (c >> 1)];
        unsigned vb1 = vtw[vbase + (c >> 1) + 4];
        mma_16x8x16(o0, o1, o2, o3, a0, a1, a2, a3, vb0, vb1);
    }

    // ---- row sums: reduce across the 4 lanes of each quad ----
    L0 += __shfl_xor_sync(0xffffffffu, L0, 1);
    L0 += __shfl_xor_sync(0xffffffffu, L0, 2);
    L1 += __shfl_xor_sync(0xffffffffu, L1, 1);
    L1 += __shfl_xor_sync(0xffffffffu, L1, 2);
    float inv0 = 1.f / L0;
    float inv1 = 1.f / L1;

    // ---- write O: rows r0+qr, r0+qr+8; dims 2*qm, 2*qm+1 ----
    {
        int s0 = r0 + qr;
        float2* p0 = (float2*)&g_ao[((((size_t)b << 10) + s0) << 6) + (h << 3) + (qm << 1)];
        *p0 = make_float2(o0 * inv0, o1 * inv0);
        int s1 = s0 + 8;
        float2* p1 = (float2*)&g_ao[((((size_t)b << 10) + s1) << 6) + (h << 3) + (qm << 1)];
        *p1 = make_float2(o2 * inv1, o3 * inv1);
    }
}

// ---------------------------------------------------------------------------
// Epilogue: out = ao @ W^T + b.  W rows in REGISTERS (lane owns column e);
// activations staged linearly in smem, read via warp-broadcast ld.shared.v4.
// Grid 128 x 64 rows (R4 config: 9.2us).
// ---------------------------------------------------------------------------
__global__ __launch_bounds__(256) void epilogue_kernel(const float* __restrict__ W,
                                                       const float* __restrict__ bias,
                                                       float* __restrict__ out) {
    __shared__ float ssin[64 * 64];      // 16 KB

    const int tid = threadIdx.x;
    const int row0 = blockIdx.x * 64;

    const float4* src = (const float4*)(g_ao + (size_t)row0 * 64);
    float4* dst = (float4*)ssin;
    #pragma unroll
    for (int i = 0; i < 4; i++)
        dst[tid + i * 256] = src[tid + i * 256];

    const int w = tid >> 5, lane = tid & 31;
    const int e = (w & 1) * 32 + lane;
    float wreg[64];
    const float4* wsrc = (const float4*)(W + e * 64);
    #pragma unroll
    for (int i = 0; i < 16; i++) {
        float4 v = wsrc[i];
        wreg[4 * i + 0] = v.x;
        wreg[4 * i + 1] = v.y;
        wreg[4 * i + 2] = v.z;
        wreg[4 * i + 3] = v.w;
    }
    const float be = bias[e];
    __syncthreads();

    const int rbase = (w >> 1) * 16;
    #pragma unroll 2
    for (int rr = 0; rr < 16; rr++) {
        int r = rbase + rr;
        const float4* srow = (const float4*)&ssin[r * 64];
        float acc = be;
        #pragma unroll
        for (int i = 0; i < 16; i++) {
            float4 sv = srow[i];
            acc += sv.x * wreg[4 * i + 0];
            acc += sv.y * wreg[4 * i + 1];
            acc += sv.z * wreg[4 * i + 2];
            acc += sv.w * wreg[4 * i + 3];
        }
        out[(row0 + r) * 64 + e] = acc;
    }
}

// ---------------------------------------------------------------------------
extern "C" void kernel_launch(void* const* d_in, const int* in_sizes, int n_in,
                              void* d_out, int out_size) {
    const float* x    = (const float*)d_in[0];
    const float* phi  = (const float*)d_in[1];
    const float* W    = (const float*)d_in[2];
    const float* bias = (const float*)d_in[3];
    float* out = (float*)d_out;

    cudaFuncSetAttribute(attn_kernel, cudaFuncAttributeMaxDynamicSharedMemorySize,
                         SMEM_BYTES);
    attn_kernel<<<BH * 8, 256, SMEM_BYTES>>>(x, phi);
    epilogue_kernel<<<(BB * SS) / 64, 256>>>(W, bias, out);
}

// round 7
// speedup vs baseline: 2.7150x; 1.0476x over previous
#include <cuda_runtime.h>
#include <cuda_fp16.h>

#define SS   1024
#define BB   8
#define NH   8
#define BH   (BB * NH)          // 64

// Scratch: attention out in ROW-FEATURE layout [b*1024+s][h*8+d]  (2 MB)
__device__ float g_ao[BB * SS * 64];

// smem partition (dynamic): kh[1024][8] half, kl[1024][8] half, vt[8][1032] half
#define SM_KH 0
#define SM_KL 16384
#define SM_VT 32768
#define VT_STRIDE 1032              // halves per d-row: bank-free PV b-frags
#define SMEM_BYTES (32768 + 8 * VT_STRIDE * 2)   // 49280

__device__ __forceinline__ float ex2(float x) {
    float r; asm("ex2.approx.f32 %0,%1;" : "=f"(r) : "f"(x)); return r;
}
__device__ __forceinline__ unsigned h2pk(float hi, float lo) {
    unsigned r; asm("cvt.rn.f16x2.f32 %0,%1,%2;" : "=r"(r) : "f"(hi), "f"(lo)); return r;
}
__device__ __forceinline__ void mma_16x8x8(float& c0, float& c1, float& c2, float& c3,
                                           unsigned a0, unsigned a1, unsigned b0) {
    asm("mma.sync.aligned.m16n8k8.row.col.f32.f16.f16.f32 "
        "{%0,%1,%2,%3},{%4,%5},{%6},{%0,%1,%2,%3};"
        : "+f"(c0), "+f"(c1), "+f"(c2), "+f"(c3)
        : "r"(a0), "r"(a1), "r"(b0));
}
__device__ __forceinline__ void mma_16x8x16(float& c0, float& c1, float& c2, float& c3,
                                            unsigned a0, unsigned a1, unsigned a2, unsigned a3,
                                            unsigned b0, unsigned b1) {
    asm("mma.sync.aligned.m16n8k16.row.col.f32.f16.f16.f32 "
        "{%0,%1,%2,%3},{%4,%5,%6,%7},{%8,%9},{%0,%1,%2,%3};"
        : "+f"(c0), "+f"(c1), "+f"(c2), "+f"(c3)
        : "r"(a0), "r"(a1), "r"(a2), "r"(a3), "r"(b0), "r"(b1));
}

// Empty kernels: shift ncu's `-s 5` capture onto attn (position 1 mod 4).
__global__ void nop_kernel() {}

// ---------------------------------------------------------------------------
// Fused qlayer + flash-attention via mma.sync.
// QK = qh*(kh+kl) (2 mmas per 8 keys): residual err (q-fp16(q))*k ~1e-4.
// 32-key pipeline stages: all QK mmas -> all ex2 -> both PV mmas, so the
// tensor and MUFU pipes overlap across stages instead of serializing.
// Grid: 512 blocks = 64 heads x 8 row-tiles; 256 thr = 8 warps x 16 q-rows.
// ---------------------------------------------------------------------------
__global__ __launch_bounds__(256) void attn_kernel(const float* __restrict__ x,
                                                   const float* __restrict__ phi) {
    extern __shared__ char dynsmem[];
    __half*  kh = (__half*)(dynsmem + SM_KH);       // [j][8] row-major
    __half*  kl = (__half*)(dynsmem + SM_KL);       // [j][8] row-major
    __half*  vt = (__half*)(dynsmem + SM_VT);       // [d][VT_STRIDE]
    const unsigned* khw = (const unsigned*)kh;      // half2 words: [j*4 + p]
    const unsigned* klw = (const unsigned*)kl;
    const unsigned* vtw = (const unsigned*)vt;      // [d*516 + j/2]

    const int bh = blockIdx.x >> 3;
    const int b = bh >> 3, h = bh & 7;
    const int tid = threadIdx.x;

    float ph0 = phi[0], ph1 = phi[1], ph2 = phi[2], ph3 = phi[3];
    float ph4 = phi[4], ph5 = phi[5], ph6 = phi[6], ph7 = phi[7];

    // ---- prologue: qlayer -> kh/kl (row-major) and vt (transposed) ----
    #pragma unroll
    for (int it = 0; it < 4; it++) {
        int s = tid + it * 256;
        const float4* xp = (const float4*)(x + ((size_t)((b << 10) + s) << 6) + (h << 3));
        float4 xa = xp[0];
        float4 xb = xp[1];
        float k0 = __cosf(xa.x + ph0);
        float c1 = __cosf(xa.y + ph1);
        float c2 = __cosf(xa.z + ph2);
        float c3 = __cosf(xa.w + ph3);
        float c4 = __cosf(xb.x + ph4);
        float c5 = __cosf(xb.y + ph5);
        float c6 = __cosf(xb.z + ph6);
        float c7 = __cosf(xb.w + ph7);
        float kv[8];
        kv[1] = k0 * c1;
        kv[2] = kv[1] * c2;
        kv[3] = kv[2] * c3;
        kv[4] = kv[3] * c4;
        kv[5] = kv[4] * c5;
        kv[6] = kv[5] * c6;
        kv[7] = kv[6] * c7;
        float t = c1 * c2;
        t *= c3; t *= c4; t *= c5; t *= c6; t *= c7;
        kv[0] = t;
        #pragma unroll
        for (int d = 0; d < 8; d++) {
            __half hi = __float2half_rn(kv[d]);
            __half lo = __float2half_rn(kv[d] - __half2float(hi));
            kh[s * 8 + d] = hi;
            kl[s * 8 + d] = lo;
            vt[d * VT_STRIDE + s] = hi;   // V fp16 (err averages out over keys)
        }
    }
    __syncthreads();

    // ---- per-warp Q fragments (fp16 only; K side carries compensation) ----
    const int wid = tid >> 5, lane = tid & 31;
    const int r0 = ((blockIdx.x & 7) << 7) + (wid << 4);
    const int qr = lane >> 2, qm = lane & 3;
    const float SC = 0.35355339059327373f * 1.4426950408889634f;

    unsigned qh_a0, qh_a1;
    {
        #pragma unroll
        for (int half_ = 0; half_ < 2; half_++) {
            int row = r0 + qr + half_ * 8;
            unsigned wh = khw[row * 4 + qm];
            unsigned wl = klw[row * 4 + qm];
            __half2 hh = *(__half2*)&wh, hl = *(__half2*)&wl;
            float q0 = (__half2float(hh.x) + __half2float(hl.x)) * SC;
            float q1 = (__half2float(hh.y) + __half2float(hl.y)) * SC;
            unsigned ah = h2pk(q1, q0);
            if (half_ == 0) qh_a0 = ah; else qh_a1 = ah;
        }
    }

    float o0 = 0.f, o1 = 0.f, o2 = 0.f, o3 = 0.f;   // O accum (16x8)
    float L0 = 0.f, L1 = 0.f;                        // row-sum partials

    const int vbase = (lane >> 2) * (VT_STRIDE / 2) + (lane & 3);

    for (int c = 0; c < SS; c += 32) {
        // ---- stage 1: all b-frag loads for 32 keys ----
        unsigned bh0 = khw[(c +  0) * 4 + lane], bl0 = klw[(c +  0) * 4 + lane];
        unsigned bh1 = khw[(c +  8) * 4 + lane], bl1 = klw[(c +  8) * 4 + lane];
        unsigned bh2 = khw[(c + 16) * 4 + lane], bl2 = klw[(c + 16) * 4 + lane];
        unsigned bh3 = khw[(c + 24) * 4 + lane], bl3 = klw[(c + 24) * 4 + lane];

        // ---- stage 2: 8 QK mmas (4 groups x 2) ----
        float s00=0.f,s01=0.f,s02=0.f,s03=0.f;
        float s10=0.f,s11=0.f,s12=0.f,s13=0.f;
        float s20=0.f,s21=0.f,s22=0.f,s23=0.f;
        float s30=0.f,s31=0.f,s32=0.f,s33=0.f;
        mma_16x8x8(s00,s01,s02,s03, qh_a0,qh_a1, bh0);
        mma_16x8x8(s10,s11,s12,s13, qh_a0,qh_a1, bh1);
        mma_16x8x8(s20,s21,s22,s23, qh_a0,qh_a1, bh2);
        mma_16x8x8(s30,s31,s32,s33, qh_a0,qh_a1, bh3);
        mma_16x8x8(s00,s01,s02,s03, qh_a0,qh_a1, bl0);
        mma_16x8x8(s10,s11,s12,s13, qh_a0,qh_a1, bl1);
        mma_16x8x8(s20,s21,s22,s23, qh_a0,qh_a1, bl2);
        mma_16x8x8(s30,s31,s32,s33, qh_a0,qh_a1, bl3);

        // ---- stage 3: 16 ex2 (no max-sub: |s| <= 4.1 log2-units) ----
        float p00=ex2(s00),p01=ex2(s01),p02=ex2(s02),p03=ex2(s03);
        float p10=ex2(s10),p11=ex2(s11),p12=ex2(s12),p13=ex2(s13);
        float p20=ex2(s20),p21=ex2(s21),p22=ex2(s22),p23=ex2(s23);
        float p30=ex2(s30),p31=ex2(s31),p32=ex2(s32),p33=ex2(s33);

        L0 += (p00 + p01) + (p10 + p11) + (p20 + p21) + (p30 + p31);
        L1 += (p02 + p03) + (p12 + p13) + (p22 + p23) + (p32 + p33);

        // ---- stage 4: pack P fp16 A-frags, 2 PV mmas ----
        unsigned a00 = h2pk(p01, p00), a01 = h2pk(p03, p02);
        unsigned a10 = h2pk(p11, p10), a11 = h2pk(p13, p12);
        unsigned a20 = h2pk(p21, p20), a21 = h2pk(p23, p22);
        unsigned a30 = h2pk(p31, p30), a31 = h2pk(p33, p32);

        unsigned vb0 = vtw[vbase + (c >> 1)];
        unsigned vb1 = vtw[vbase + (c >> 1) + 4];
        unsigned vb2 = vtw[vbase + (c >> 1) + 8];
        unsigned vb3 = vtw[vbase + (c >> 1) + 12];
        mma_16x8x16(o0, o1, o2, o3, a00, a01, a10, a11, vb0, vb1);
        mma_16x8x16(o0, o1, o2, o3, a20, a21, a30, a31, vb2, vb3);
    }

    // ---- row sums: reduce across the 4 lanes of each quad ----
    L0 += __shfl_xor_sync(0xffffffffu, L0, 1);
    L0 += __shfl_xor_sync(0xffffffffu, L0, 2);
    L1 += __shfl_xor_sync(0xffffffffu, L1, 1);
    L1 += __shfl_xor_sync(0xffffffffu, L1, 2);
    float inv0 = 1.f / L0;
    float inv1 = 1.f / L1;

    // ---- write O: rows r0+qr, r0+qr+8; dims 2*qm, 2*qm+1 ----
    {
        int s0 = r0 + qr;
        float2* p0 = (float2*)&g_ao[((((size_t)b << 10) + s0) << 6) + (h << 3) + (qm << 1)];
        *p0 = make_float2(o0 * inv0, o1 * inv0);
        int s1 = s0 + 8;
        float2* p1 = (float2*)&g_ao[((((size_t)b << 10) + s1) << 6) + (h << 3) + (qm << 1)];
        *p1 = make_float2(o2 * inv1, o3 * inv1);
    }
}

// ---------------------------------------------------------------------------
// Epilogue: out = ao @ W^T + b.  W rows in REGISTERS (lane owns column e).
// 4 rows in flight per thread -> 4 independent FMA chains (was 1: serial
// 64x4-cyc chain was the bottleneck at occ 12%).
// ---------------------------------------------------------------------------
__global__ __launch_bounds__(256) void epilogue_kernel(const float* __restrict__ W,
                                                       const float* __restrict__ bias,
                                                       float* __restrict__ out) {
    __shared__ float ssin[64 * 64];      // 16 KB

    const int tid = threadIdx.x;
    const int row0 = blockIdx.x * 64;

    const float4* src = (const float4*)(g_ao + (size_t)row0 * 64);
    float4* dst = (float4*)ssin;
    #pragma unroll
    for (int i = 0; i < 4; i++)
        dst[tid + i * 256] = src[tid + i * 256];

    const int w = tid >> 5, lane = tid & 31;
    const int e = (w & 1) * 32 + lane;
    float wreg[64];
    const float4* wsrc = (const float4*)(W + e * 64);
    #pragma unroll
    for (int i = 0; i < 16; i++) {
        float4 v = wsrc[i];
        wreg[4 * i + 0] = v.x;
        wreg[4 * i + 1] = v.y;
        wreg[4 * i + 2] = v.z;
        wreg[4 * i + 3] = v.w;
    }
    const float be = bias[e];
    __syncthreads();

    const int rbase = (w >> 1) * 16;
    #pragma unroll
    for (int rr = 0; rr < 16; rr += 4) {
        const float4* s0 = (const float4*)&ssin[(rbase + rr + 0) * 64];
        const float4* s1 = (const float4*)&ssin[(rbase + rr + 1) * 64];
        const float4* s2 = (const float4*)&ssin[(rbase + rr + 2) * 64];
        const float4* s3 = (const float4*)&ssin[(rbase + rr + 3) * 64];
        float a0 = be, a1 = be, a2 = be, a3 = be;
        #pragma unroll
        for (int i = 0; i < 16; i++) {
            float4 v0 = s0[i], v1 = s1[i], v2 = s2[i], v3 = s3[i];
            a0 += v0.x * wreg[4*i+0]; a0 += v0.y * wreg[4*i+1];
            a0 += v0.z * wreg[4*i+2]; a0 += v0.w * wreg[4*i+3];
            a1 += v1.x * wreg[4*i+0]; a1 += v1.y * wreg[4*i+1];
            a1 += v1.z * wreg[4*i+2]; a1 += v1.w * wreg[4*i+3];
            a2 += v2.x * wreg[4*i+0]; a2 += v2.y * wreg[4*i+1];
            a2 += v2.z * wreg[4*i+2]; a2 += v2.w * wreg[4*i+3];
            a3 += v3.x * wreg[4*i+0]; a3 += v3.y * wreg[4*i+1];
            a3 += v3.z * wreg[4*i+2]; a3 += v3.w * wreg[4*i+3];
        }
        int r = row0 + rbase + rr;
        out[(r + 0) * 64 + e] = a0;
        out[(r + 1) * 64 + e] = a1;
        out[(r + 2) * 64 + e] = a2;
        out[(r + 3) * 64 + e] = a3;
    }
}

// ---------------------------------------------------------------------------
extern "C" void kernel_launch(void* const* d_in, const int* in_sizes, int n_in,
                              void* d_out, int out_size) {
    const float* x    = (const float*)d_in[0];
    const float* phi  = (const float*)d_in[1];
    const float* W    = (const float*)d_in[2];
    const float* bias = (const float*)d_in[3];
    float* out = (float*)d_out;

    cudaFuncSetAttribute(attn_kernel, cudaFuncAttributeMaxDynamicSharedMemorySize,
                         SMEM_BYTES);
    nop_kernel<<<1, 32>>>();                         // pos 0 (mod 4)
    attn_kernel<<<BH * 8, 256, SMEM_BYTES>>>(x, phi); // pos 1 -> ncu -s 5 lands here
    epilogue_kernel<<<(BB * SS) / 64, 256>>>(W, bias, out); // pos 2
    nop_kernel<<<1, 32>>>();                         // pos 3
}

// round 8
// speedup vs baseline: 2.8530x; 1.0508x over previous
#include <cuda_runtime.h>
#include <cuda_fp16.h>

#define SS   1024
#define BB   8
#define NH   8
#define BH   (BB * NH)          // 64

// Scratch: attention out in ROW-FEATURE layout [b*1024+s][h*8+d]  (2 MB)
__device__ float g_ao[BB * SS * 64];

// smem partition (dynamic): kh[1024][8] half, kl[1024][8] half, vt[8][1032] half
#define SM_KH 0
#define SM_KL 16384
#define SM_VT 32768
#define VT_STRIDE 1032              // halves per d-row: bank-free PV b-frags
#define SMEM_BYTES (32768 + 8 * VT_STRIDE * 2)   // 49280

#define ONES_H2 0x3C003C00u         // fp16x2 (1.0, 1.0)

__device__ __forceinline__ unsigned h2pk(float hi, float lo) {
    unsigned r; asm("cvt.rn.f16x2.f32 %0,%1,%2;" : "=r"(r) : "f"(hi), "f"(lo)); return r;
}
__device__ __forceinline__ unsigned ex2h2(unsigned x) {
    unsigned r; asm("ex2.approx.f16x2 %0,%1;" : "=r"(r) : "r"(x)); return r;
}
__device__ __forceinline__ void mma_16x8x8(float& c0, float& c1, float& c2, float& c3,
                                           unsigned a0, unsigned a1, unsigned b0) {
    asm("mma.sync.aligned.m16n8k8.row.col.f32.f16.f16.f32 "
        "{%0,%1,%2,%3},{%4,%5},{%6},{%0,%1,%2,%3};"
        : "+f"(c0), "+f"(c1), "+f"(c2), "+f"(c3)
        : "r"(a0), "r"(a1), "r"(b0));
}
__device__ __forceinline__ void mma_16x8x16(float& c0, float& c1, float& c2, float& c3,
                                            unsigned a0, unsigned a1, unsigned a2, unsigned a3,
                                            unsigned b0, unsigned b1) {
    asm("mma.sync.aligned.m16n8k16.row.col.f32.f16.f16.f32 "
        "{%0,%1,%2,%3},{%4,%5,%6,%7},{%8,%9},{%0,%1,%2,%3};"
        : "+f"(c0), "+f"(c1), "+f"(c2), "+f"(c3)
        : "r"(a0), "r"(a1), "r"(a2), "r"(a3), "r"(b0), "r"(b1));
}

// ---------------------------------------------------------------------------
// Fused qlayer + flash-attention via mma.sync.
// QK = qh*(kh+kl) (2 mmas per 8 keys). Softmax weights via ex2.approx.f16x2
// (packed fp16 MUFU: half the MUFU work, result IS the PV A-frag).
// Row-sums L computed by an extra mma with B==1 (f32 accum, no shuffles).
// Grid: 512 blocks = 64 heads x 8 row-tiles; 256 thr = 8 warps x 16 q-rows.
// ---------------------------------------------------------------------------
__global__ __launch_bounds__(256) void attn_kernel(const float* __restrict__ x,
                                                   const float* __restrict__ phi) {
    extern __shared__ char dynsmem[];
    __half*  kh = (__half*)(dynsmem + SM_KH);       // [j][8] row-major
    __half*  kl = (__half*)(dynsmem + SM_KL);       // [j][8] row-major
    __half*  vt = (__half*)(dynsmem + SM_VT);       // [d][VT_STRIDE]
    const unsigned* khw = (const unsigned*)kh;      // half2 words: [j*4 + p]
    const unsigned* klw = (const unsigned*)kl;
    const unsigned* vtw = (const unsigned*)vt;      // [d*516 + j/2]

    const int bh = blockIdx.x >> 3;
    const int b = bh >> 3, h = bh & 7;
    const int tid = threadIdx.x;

    float ph0 = phi[0], ph1 = phi[1], ph2 = phi[2], ph3 = phi[3];
    float ph4 = phi[4], ph5 = phi[5], ph6 = phi[6], ph7 = phi[7];

    // ---- prologue: qlayer (prefix products of cos) -> kh/kl and vt ----
    #pragma unroll
    for (int it = 0; it < 4; it++) {
        int s = tid + it * 256;
        const float4* xp = (const float4*)(x + ((size_t)((b << 10) + s) << 6) + (h << 3));
        float4 xa = xp[0];
        float4 xb = xp[1];
        float k0 = __cosf(xa.x + ph0);
        float c1 = __cosf(xa.y + ph1);
        float c2 = __cosf(xa.z + ph2);
        float c3 = __cosf(xa.w + ph3);
        float c4 = __cosf(xb.x + ph4);
        float c5 = __cosf(xb.y + ph5);
        float c6 = __cosf(xb.z + ph6);
        float c7 = __cosf(xb.w + ph7);
        float kv[8];
        kv[1] = k0 * c1;
        kv[2] = kv[1] * c2;
        kv[3] = kv[2] * c3;
        kv[4] = kv[3] * c4;
        kv[5] = kv[4] * c5;
        kv[6] = kv[5] * c6;
        kv[7] = kv[6] * c7;
        float t = c1 * c2;
        t *= c3; t *= c4; t *= c5; t *= c6; t *= c7;
        kv[0] = t;
        #pragma unroll
        for (int d = 0; d < 8; d++) {
            __half hi = __float2half_rn(kv[d]);
            __half lo = __float2half_rn(kv[d] - __half2float(hi));
            kh[s * 8 + d] = hi;
            kl[s * 8 + d] = lo;
            vt[d * VT_STRIDE + s] = hi;   // V fp16 (err averages out over keys)
        }
    }
    __syncthreads();

    // ---- per-warp Q fragments (fp16; K side carries the compensation) ----
    const int wid = tid >> 5, lane = tid & 31;
    const int r0 = ((blockIdx.x & 7) << 7) + (wid << 4);
    const int qr = lane >> 2, qm = lane & 3;
    const float SC = 0.35355339059327373f * 1.4426950408889634f;

    unsigned qh_a0, qh_a1;
    {
        #pragma unroll
        for (int half_ = 0; half_ < 2; half_++) {
            int row = r0 + qr + half_ * 8;
            unsigned wh = khw[row * 4 + qm];
            unsigned wl = klw[row * 4 + qm];
            __half2 hh = *(__half2*)&wh, hl = *(__half2*)&wl;
            float q0 = (__half2float(hh.x) + __half2float(hl.x)) * SC;
            float q1 = (__half2float(hh.y) + __half2float(hl.y)) * SC;
            unsigned ah = h2pk(q1, q0);
            if (half_ == 0) qh_a0 = ah; else qh_a1 = ah;
        }
    }

    float o0 = 0.f, o1 = 0.f, o2 = 0.f, o3 = 0.f;   // O accum (16x8)
    float l0 = 0.f, l1 = 0.f, l2 = 0.f, l3 = 0.f;   // L via ones-mma

    const int vbase = (lane >> 2) * (VT_STRIDE / 2) + (lane & 3);

    for (int c = 0; c < SS; c += 32) {
        // ---- b-frag loads for 32 keys ----
        unsigned bh0 = khw[(c +  0) * 4 + lane], bl0 = klw[(c +  0) * 4 + lane];
        unsigned bh1 = khw[(c +  8) * 4 + lane], bl1 = klw[(c +  8) * 4 + lane];
        unsigned bh2 = khw[(c + 16) * 4 + lane], bl2 = klw[(c + 16) * 4 + lane];
        unsigned bh3 = khw[(c + 24) * 4 + lane], bl3 = klw[(c + 24) * 4 + lane];

        // ---- 8 QK mmas ----
        float s00=0.f,s01=0.f,s02=0.f,s03=0.f;
        float s10=0.f,s11=0.f,s12=0.f,s13=0.f;
        float s20=0.f,s21=0.f,s22=0.f,s23=0.f;
        float s30=0.f,s31=0.f,s32=0.f,s33=0.f;
        mma_16x8x8(s00,s01,s02,s03, qh_a0,qh_a1, bh0);
        mma_16x8x8(s10,s11,s12,s13, qh_a0,qh_a1, bh1);
        mma_16x8x8(s20,s21,s22,s23, qh_a0,qh_a1, bh2);
        mma_16x8x8(s30,s31,s32,s33, qh_a0,qh_a1, bh3);
        mma_16x8x8(s00,s01,s02,s03, qh_a0,qh_a1, bl0);
        mma_16x8x8(s10,s11,s12,s13, qh_a0,qh_a1, bl1);
        mma_16x8x8(s20,s21,s22,s23, qh_a0,qh_a1, bl2);
        mma_16x8x8(s30,s31,s32,s33, qh_a0,qh_a1, bl3);

        // ---- pack scores to fp16x2, then packed ex2 (8 MUFU, not 16) ----
        unsigned a00 = ex2h2(h2pk(s01, s00));
        unsigned a01 = ex2h2(h2pk(s03, s02));
        unsigned a10 = ex2h2(h2pk(s11, s10));
        unsigned a11 = ex2h2(h2pk(s13, s12));
        unsigned a20 = ex2h2(h2pk(s21, s20));
        unsigned a21 = ex2h2(h2pk(s23, s22));
        unsigned a30 = ex2h2(h2pk(s31, s30));
        unsigned a31 = ex2h2(h2pk(s33, s32));

        // ---- PV (2 mmas) + L row-sums via B==1 (2 mmas, f32 accum) ----
        unsigned vb0 = vtw[vbase + (c >> 1)];
        unsigned vb1 = vtw[vbase + (c >> 1) + 4];
        unsigned vb2 = vtw[vbase + (c >> 1) + 8];
        unsigned vb3 = vtw[vbase + (c >> 1) + 12];
        mma_16x8x16(o0, o1, o2, o3, a00, a01, a10, a11, vb0, vb1);
        mma_16x8x16(o0, o1, o2, o3, a20, a21, a30, a31, vb2, vb3);
        mma_16x8x16(l0, l1, l2, l3, a00, a01, a10, a11, ONES_H2, ONES_H2);
        mma_16x8x16(l0, l1, l2, l3, a20, a21, a30, a31, ONES_H2, ONES_H2);
    }

    // every column of the L mma equals the row-sum: no reduction needed
    float inv0 = 1.f / l0;
    float inv1 = 1.f / l2;

    // ---- write O: rows r0+qr, r0+qr+8; dims 2*qm, 2*qm+1 ----
    {
        int s0 = r0 + qr;
        float2* p0 = (float2*)&g_ao[((((size_t)b << 10) + s0) << 6) + (h << 3) + (qm << 1)];
        *p0 = make_float2(o0 * inv0, o1 * inv0);
        int s1 = s0 + 8;
        float2* p1 = (float2*)&g_ao[((((size_t)b << 10) + s1) << 6) + (h << 3) + (qm << 1)];
        *p1 = make_float2(o2 * inv1, o3 * inv1);
    }
}

// ---------------------------------------------------------------------------
// Epilogue: out = ao @ W^T + b.  W rows in REGISTERS (lane owns column e);
// 4 rows in flight per thread -> 4 independent FMA chains.
// ---------------------------------------------------------------------------
__global__ __launch_bounds__(256) void epilogue_kernel(const float* __restrict__ W,
                                                       const float* __restrict__ bias,
                                                       float* __restrict__ out) {
    __shared__ float ssin[64 * 64];      // 16 KB

    const int tid = threadIdx.x;
    const int row0 = blockIdx.x * 64;

    const float4* src = (const float4*)(g_ao + (size_t)row0 * 64);
    float4* dst = (float4*)ssin;
    #pragma unroll
    for (int i = 0; i < 4; i++)
        dst[tid + i * 256] = src[tid + i * 256];

    const int w = tid >> 5, lane = tid & 31;
    const int e = (w & 1) * 32 + lane;
    float wreg[64];
    const float4* wsrc = (const float4*)(W + e * 64);
    #pragma unroll
    for (int i = 0; i < 16; i++) {
        float4 v = wsrc[i];
        wreg[4 * i + 0] = v.x;
        wreg[4 * i + 1] = v.y;
        wreg[4 * i + 2] = v.z;
        wreg[4 * i + 3] = v.w;
    }
    const float be = bias[e];
    __syncthreads();

    const int rbase = (w >> 1) * 16;
    #pragma unroll
    for (int rr = 0; rr < 16; rr += 4) {
        const float4* s0 = (const float4*)&ssin[(rbase + rr + 0) * 64];
        const float4* s1 = (const float4*)&ssin[(rbase + rr + 1) * 64];
        const float4* s2 = (const float4*)&ssin[(rbase + rr + 2) * 64];
        const float4* s3 = (const float4*)&ssin[(rbase + rr + 3) * 64];
        float a0 = be, a1 = be, a2 = be, a3 = be;
        #pragma unroll
        for (int i = 0; i < 16; i++) {
            float4 v0 = s0[i], v1 = s1[i], v2 = s2[i], v3 = s3[i];
            a0 += v0.x * wreg[4*i+0]; a0 += v0.y * wreg[4*i+1];
            a0 += v0.z * wreg[4*i+2]; a0 += v0.w * wreg[4*i+3];
            a1 += v1.x * wreg[4*i+0]; a1 += v1.y * wreg[4*i+1];
            a1 += v1.z * wreg[4*i+2]; a1 += v1.w * wreg[4*i+3];
            a2 += v2.x * wreg[4*i+0]; a2 += v2.y * wreg[4*i+1];
            a2 += v2.z * wreg[4*i+2]; a2 += v2.w * wreg[4*i+3];
            a3 += v3.x * wreg[4*i+0]; a3 += v3.y * wreg[4*i+1];
            a3 += v3.z * wreg[4*i+2]; a3 += v3.w * wreg[4*i+3];
        }
        int r = row0 + rbase + rr;
        out[(r + 0) * 64 + e] = a0;
        out[(r + 1) * 64 + e] = a1;
        out[(r + 2) * 64 + e] = a2;
        out[(r + 3) * 64 + e] = a3;
    }
}

// ---------------------------------------------------------------------------
extern "C" void kernel_launch(void* const* d_in, const int* in_sizes, int n_in,
                              void* d_out, int out_size) {
    const float* x    = (const float*)d_in[0];
    const float* phi  = (const float*)d_in[1];
    const float* W    = (const float*)d_in[2];
    const float* bias = (const float*)d_in[3];
    float* out = (float*)d_out;

    cudaFuncSetAttribute(attn_kernel, cudaFuncAttributeMaxDynamicSharedMemorySize,
                         SMEM_BYTES);
    attn_kernel<<<BH * 8, 256, SMEM_BYTES>>>(x, phi);
    epilogue_kernel<<<(BB * SS) / 64, 256>>>(W, bias, out);
}